// round 11
// baseline (speedup 1.0000x reference)
#include <cuda_runtime.h>

// out[b,u] = prod_f(in[b,f]*w[f,u]) + bias[u] = P[b]*W[u] + bias[u]
// B=32768, F=32, U=256.
static constexpr int Bn = 32768;
static constexpr int Fn = 32;
static constexpr int Un = 256;

static constexpr int ROWS_PER_TILE = 64;          // 16 warps * 4 rows
static constexpr int NT   = Bn / ROWS_PER_TILE;   // 512 tiles
static constexpr int GRID = 296;                  // exactly 2 blocks per SM (148 SMs)
static constexpr int THREADS = 512;

// Packed fp32x2 helpers (Blackwell sm_103a; FFMA2 only reachable via PTX).
__device__ __forceinline__ unsigned long long pk2(float lo, float hi) {
    unsigned long long r;
    asm("mov.b64 %0, {%1, %2};" : "=l"(r) : "f"(lo), "f"(hi));
    return r;
}
__device__ __forceinline__ unsigned long long fma2(unsigned long long a,
                                                   unsigned long long b,
                                                   unsigned long long c) {
    unsigned long long d;
    asm("fma.rn.f32x2 %0, %1, %2, %3;" : "=l"(d) : "l"(a), "l"(b), "l"(c));
    return d;
}

// Persistent-ish fused kernel:
//   - W[u] = prod_f w[f,u] computed ONCE per block (threads 0..255) into smem
//   - W and bias then promoted to registers (lane owns 8 columns) and reused
//     across ALL grid-stride iterations -> no per-iteration W/bias traffic
//   - each warp per iteration: 1 coalesced float4 input load (4 rows),
//     3 shfl_xor row-product reduce, 4x(bcast + 4 FFMA2 + 2 STG.128)
//   - no barriers inside the loop; iterations independent -> LDGs overlap
__global__ __launch_bounds__(THREADS)
void fused_kernel(const float* __restrict__ in,
                  const float* __restrict__ w,
                  const float* __restrict__ bias,
                  float* __restrict__ out) {
    __shared__ float sW[Un];

    const int t    = threadIdx.x;
    const int lane = t & 31;
    const int warp = t >> 5;          // 0..15

    // ---- one-time W phase (threads 0..255, column t) ----
    if (t < Un) {
        float p0 = 1.0f, p1 = 1.0f, p2 = 1.0f, p3 = 1.0f;
#pragma unroll
        for (int f = 0; f < Fn; f += 4) {
            p0 *= w[(f + 0) * Un + t];
            p1 *= w[(f + 1) * Un + t];
            p2 *= w[(f + 2) * Un + t];
            p3 *= w[(f + 3) * Un + t];
        }
        sW[t] = (p0 * p1) * (p2 * p3);
    }

    // bias -> regs (independent of W phase, overlaps it)
    const float4* B4 = reinterpret_cast<const float4*>(bias);
    const float4 bv0 = B4[lane];
    const float4 bv1 = B4[lane + 32];

    __syncthreads();

    // W -> regs (lane owns float4 columns `lane` and `lane+32`)
    const float4* sW4 = reinterpret_cast<const float4*>(sW);
    const float4 wv0 = sW4[lane];
    const float4 wv1 = sW4[lane + 32];

    // pack W/bias into f32x2 operands once
    const unsigned long long w00 = pk2(wv0.x, wv0.y), w01 = pk2(wv0.z, wv0.w);
    const unsigned long long w10 = pk2(wv1.x, wv1.y), w11 = pk2(wv1.z, wv1.w);
    const unsigned long long b00 = pk2(bv0.x, bv0.y), b01 = pk2(bv0.z, bv0.w);
    const unsigned long long b10 = pk2(bv1.x, bv1.y), b11 = pk2(bv1.z, bv1.w);

    // ---- grid-stride over 512 tiles of 64 rows ----
    for (int tile = blockIdx.x; tile < NT; tile += GRID) {
        const long long rowbase = (long long)tile * ROWS_PER_TILE + warp * 4;

        // 4 rows * 32 f = 32 float4; lane l covers row l>>3 (8 lanes/row)
        const float4* in4 = reinterpret_cast<const float4*>(in + rowbase * Fn);
        const float4 v = in4[lane];
        float p = v.x * v.y * v.z * v.w;
        p *= __shfl_xor_sync(0xffffffffu, p, 1);
        p *= __shfl_xor_sync(0xffffffffu, p, 2);
        p *= __shfl_xor_sync(0xffffffffu, p, 4);
        // lanes 8r..8r+7 hold product of row (rowbase + r)

        // row stride = 256 floats = 64 x 16B
        ulonglong2* out2 = reinterpret_cast<ulonglong2*>(out + rowbase * Un);
#pragma unroll
        for (int r = 0; r < 4; ++r) {
            const float pr = __shfl_sync(0xffffffffu, p, r * 8);
            const unsigned long long pp = pk2(pr, pr);
            ulonglong2 o0, o1;
            o0.x = fma2(pp, w00, b00);
            o0.y = fma2(pp, w01, b01);
            o1.x = fma2(pp, w10, b10);
            o1.y = fma2(pp, w11, b11);
            out2[r * 64 + lane]      = o0;   // coalesced 128B/warp
            out2[r * 64 + lane + 32] = o1;
        }
    }
}

extern "C" void kernel_launch(void* const* d_in, const int* in_sizes, int n_in,
                              void* d_out, int out_size) {
    // metadata order: inputs [B,F], weight [F,U], weight_selector [F,U] (dead), bias [U]
    const float* in   = (const float*)d_in[0];
    const float* w    = (const float*)d_in[1];
    const float* bias = (const float*)d_in[3];
    float* out        = (float*)d_out;

    fused_kernel<<<GRID, THREADS>>>(in, w, bias, out);
}